// round 4
// baseline (speedup 1.0000x reference)
#include <cuda_runtime.h>
#include <math.h>

// Problem constants (fixed by the reference setup)
#define Bc 8
#define Mc 384
#define Nc 1536
#define Lc 20
#define RWc 8
#define Ec (Mc * RWc)   // 3072 edges
#define TPB 1024
#define EPT (Ec / TPB)  // 3 edges per thread

// Scratch (static device globals — no allocation)
__device__ int   g_edge_col[Ec];
__device__ int   g_row_cnt[Mc];
__device__ float g_loss[Bc];

// ---------------------------------------------------------------------------
// Reset per-replay state
// ---------------------------------------------------------------------------
__global__ void k_zero() {
    int t = threadIdx.x;
    if (t < Mc) g_row_cnt[t] = 0;
    if (t < Bc) g_loss[t] = 0.f;
}

// ---------------------------------------------------------------------------
// Extract sparse structure of H: for each row m, record its RWc column indices.
// Slot order within a row is arbitrary (products / scatter-adds are order-
// independent); atomic slot assignment keeps this fully parallel.
// ---------------------------------------------------------------------------
__global__ void k_extract(const float* __restrict__ H) {
    int i = blockIdx.x * TPB + threadIdx.x;   // grid covers exactly Mc*Nc
    float h = H[i];
    if (h != 0.f) {
        int m = i / Nc;
        int slot = atomicAdd(&g_row_cnt[m], 1);
        g_edge_col[m * RWc + slot] = i - m * Nc;
    }
}

// ---------------------------------------------------------------------------
// Main BP kernel: one CTA per batch element, all L layers in-kernel.
// ---------------------------------------------------------------------------
__global__ void __launch_bounds__(TPB, 1) k_main(
    const float* __restrict__ synd,      // (B, M, 1)
    const float* __restrict__ errors,    // (B, N)
    const float* __restrict__ llrs,      // (N)
    const float* __restrict__ wde,       // (L, M, N)
    const float* __restrict__ wllr,      // (L, N)
    const float* __restrict__ marg_de,   // (M, N)
    const float* __restrict__ marg_llr,  // (N)
    const float* __restrict__ resw,      // (L)
    const float* __restrict__ rhos)      // (L)
{
    __shared__ float s_S[Nc];      // per-variable weighted message sum
    __shared__ float s_bel[Nc];    // per-variable belief accumulator
    __shared__ float s_d[Ec];      // tanh(msg_en/2) per edge
    __shared__ float s_p[Mc];      // per-row tanh product
    __shared__ float s_sign[Mc];   // (1 - 2*syndrome) per row
    __shared__ float s_red[32];

    const int b = blockIdx.x;
    const int t = threadIdx.x;

    // Per-edge static data in registers (thread t owns edges t, t+1024, t+2048)
    int   ecol[EPT], erow[EPT];
    float emarg[EPT], ellr[EPT], msg[EPT];
#pragma unroll
    for (int k = 0; k < EPT; k++) {
        const int e = t + k * TPB;
        const int c = g_edge_col[e];
        const int m = e >> 3;           // RWc = 8
        ecol[k]  = c;
        erow[k]  = m;
        emarg[k] = marg_de[m * Nc + c];
        ellr[k]  = llrs[c];
        msg[k]   = 0.f;
    }
    if (t < Mc) s_sign[t] = 1.f - 2.f * synd[b * Mc + t];
    for (int n = t; n < Nc; n += TPB) { s_S[n] = 0.f; s_bel[n] = 0.f; }
    __syncthreads();

    float loss = 0.f;

    for (int l = 0; l < Lc; l++) {
        const float rw  = resw[l];
        const float rho = rhos[l];

        // Per-layer weight gathers (same addrs across the 8 CTAs -> L2 hits)
        float wd[EPT], bse[EPT];
#pragma unroll
        for (int k = 0; k < EPT; k++) {
            wd[k]  = wde[(l * Mc + erow[k]) * Nc + ecol[k]];
            bse[k] = ellr[k] * wllr[l * Nc + ecol[k]];
        }

        // Phase 1: variable-node sums S[n] = sum_m msg * w_de
#pragma unroll
        for (int k = 0; k < EPT; k++)
            atomicAdd(&s_S[ecol[k]], msg[k] * wd[k]);
        __syncthreads();

        // Phase 2: msg_en per edge, d = tanh(msg_en/2) with zero->1 fixup
        float dr[EPT];
#pragma unroll
        for (int k = 0; k < EPT; k++) {
            float me = bse[k] + s_S[ecol[k]] - msg[k];
            float d  = tanhf(0.5f * me);
            if (d == 0.f) d = 1.f;
            dr[k] = d;
            s_d[t + k * TPB] = d;
        }
        __syncthreads();

        // Phase 3: row products (edges of row m are contiguous: [8m, 8m+8))
        if (t < Mc) {
            float p = 1.f;
#pragma unroll
            for (int j = 0; j < RWc; j++) p *= s_d[t * RWc + j];
            s_p[t] = p;
        }
        __syncthreads();

        // Phase 4: check-node update (self-exclusion by division) + beliefs
#pragma unroll
        for (int k = 0; k < EPT; k++) {
            float q  = s_p[erow[k]] / dr[k];
            float nm = 2.f * atanhf(q) * s_sign[erow[k]] + rw * msg[k];
            msg[k] = nm;
            atomicAdd(&s_bel[ecol[k]], nm * emarg[k]);
        }
        __syncthreads();

        // Phase 5: per-layer loss, then re-zero accumulators for next layer
        for (int n = t; n < Nc; n += TPB) {
            float bel = s_bel[n] + llrs[n] * marg_llr[n];
            // softplus(x) = max(x,0) + log1p(exp(-|x|))
            float sp = fmaxf(bel, 0.f) + log1pf(expf(-fabsf(bel)));
            loss += rho * (sp - (1.f - errors[b * Nc + n]) * bel);
            s_bel[n] = 0.f;
            s_S[n]   = 0.f;
        }
        __syncthreads();
    }

    // Block reduction of loss -> g_loss[b]
#pragma unroll
    for (int o = 16; o; o >>= 1) loss += __shfl_down_sync(0xffffffffu, loss, o);
    if ((t & 31) == 0) s_red[t >> 5] = loss;
    __syncthreads();
    if (t < 32) {
        float v = s_red[t];
#pragma unroll
        for (int o = 16; o; o >>= 1) v += __shfl_down_sync(0xffffffffu, v, o);
        if (t == 0) g_loss[b] = v;
    }
}

// ---------------------------------------------------------------------------
// Deterministic final reduction
// ---------------------------------------------------------------------------
__global__ void k_final(float* __restrict__ out) {
    float s = 0.f;
#pragma unroll
    for (int b = 0; b < Bc; b++) s += g_loss[b];
    out[0] = s / (float)Bc;
}

// ---------------------------------------------------------------------------
extern "C" void kernel_launch(void* const* d_in, const int* in_sizes, int n_in,
                              void* d_out, int out_size) {
    const float* synd  = (const float*)d_in[0];
    const float* errs  = (const float*)d_in[1];
    const float* H     = (const float*)d_in[2];
    const float* llrs  = (const float*)d_in[3];
    const float* wde   = (const float*)d_in[4];
    const float* wllr  = (const float*)d_in[5];
    const float* mde   = (const float*)d_in[6];
    const float* mllr  = (const float*)d_in[7];
    const float* resw  = (const float*)d_in[8];
    const float* rhos  = (const float*)d_in[9];

    k_zero<<<1, 512>>>();
    k_extract<<<(Mc * Nc) / TPB, TPB>>>(H);
    k_main<<<Bc, TPB>>>(synd, errs, llrs, wde, wllr, mde, mllr, resw, rhos);
    k_final<<<1, 1>>>((float*)d_out);
}

// round 6
// speedup vs baseline: 1.9498x; 1.9498x over previous
#include <cuda_runtime.h>
#include <math.h>

// Problem constants (fixed by the reference setup)
#define Bc 8
#define Mc 384
#define Nc 1536
#define Lc 20
#define RWc 8
#define Ec (Mc * RWc)     // 3072 edges
#define TM 768            // k_main threads: 2 per row, 4 edges per thread
#define E4 (Ec / 4)       // 768 float4 groups per layer

// Static device scratch (no allocation)
__device__ int4   g_ecol4[E4];            // edge -> column, 4 per thread
__device__ float4 g_cwde4[Lc * E4];       // compact per-edge wde, edge order
__device__ float4 g_cbse4[Lc * E4];       // compact llrs[c]*wllr[l][c]
__device__ float4 g_cmarg4[E4];           // compact marg_de per edge

__device__ __forceinline__ float tanh_fast(float x) {
    float y;
    asm("tanh.approx.f32 %0, %1;" : "=f"(y) : "f"(x));
    return y;
}

// ---------------------------------------------------------------------------
// k_prep: ballot-based sparsity extraction (no atomics) + weight compaction.
// 48 blocks x 256 threads: block bb owns rows [8*bb, 8*bb+8), warp w = row.
// ---------------------------------------------------------------------------
__global__ void __launch_bounds__(256) k_prep(
    const float* __restrict__ H,
    const float* __restrict__ llrs,
    const float* __restrict__ wde,
    const float* __restrict__ wllr,
    const float* __restrict__ marg_de,
    float* __restrict__ out)
{
    const int bb = blockIdx.x, t = threadIdx.x;
    const int w = t >> 5, lane = t & 31;
    const int row = bb * 8 + w;

    // --- extract: warp scans 1536 cols in 48 ballot steps, prefetched ---
    const float* Hr = H + row * Nc;
    int base = 0;
    float v = Hr[lane];
#pragma unroll 4
    for (int step = 0; step < 48; step++) {
        float cur = v;
        if (step < 47) v = Hr[(step + 1) * 32 + lane];
        unsigned mask = __ballot_sync(0xffffffffu, cur != 0.f);
        if (cur != 0.f) {
            int slot = base + __popc(mask & ((1u << lane) - 1u));
            ((int*)g_ecol4)[row * RWc + slot] = step * 32 + lane;
        }
        base += __popc(mask);
    }
    __syncthreads();

    // --- gather: this block's 64 edges x 20 layers ---
    const int ebase = bb * 64;
    for (int i = t; i < 64 * Lc; i += 256) {
        int l  = i >> 6;
        int eo = i & 63;
        int e  = ebase + eo;
        int c  = ((int*)g_ecol4)[e];
        int m  = e >> 3;
        ((float*)g_cwde4)[l * Ec + e] = wde[(l * Mc + m) * Nc + c];
        ((float*)g_cbse4)[l * Ec + e] = llrs[c] * wllr[l * Nc + c];
        if (l == 0) ((float*)g_cmarg4)[e] = marg_de[m * Nc + c];
    }
    if (bb == 0 && t == 0) out[0] = 0.f;
}

// ---------------------------------------------------------------------------
// k_main: one CTA per batch, 768 threads, thread t owns half of row t/2
// (edges 4t..4t+3). Row product finished via one shfl_xor with partner t^1.
// 3 barriers per layer; compact weight loads software-pipelined.
// ---------------------------------------------------------------------------
__global__ void __launch_bounds__(TM, 1) k_main(
    const float* __restrict__ synd,      // (B, M, 1)
    const float* __restrict__ errors,    // (B, N)
    const float* __restrict__ llrs,      // (N)
    const float* __restrict__ marg_llr,  // (N)
    const float* __restrict__ resw,      // (L)
    const float* __restrict__ rhos,      // (L)
    float* __restrict__ out)
{
    __shared__ float s_S[Nc];      // per-variable weighted message sum
    __shared__ float s_bel[Nc];    // per-variable belief accumulator
    __shared__ float s_lm[Nc];     // llrs[n]*marg_llr[n]
    __shared__ float s_ome[Nc];    // 1 - errors[b][n]
    __shared__ float s_sign[Mc];   // (1 - 2*syndrome) per row
    __shared__ float s_rw[Lc], s_rho[Lc];
    __shared__ float s_red[TM / 32];

    const int b = blockIdx.x;
    const int t = threadIdx.x;
    const int r = t >> 1;

    const int4   c4  = g_ecol4[t];
    const float4 mg4 = g_cmarg4[t];
    float msg0 = 0.f, msg1 = 0.f, msg2 = 0.f, msg3 = 0.f;

    if (t < Mc) s_sign[t] = 1.f - 2.f * synd[b * Mc + t];
    if (t < Lc) { s_rw[t] = resw[t]; s_rho[t] = rhos[t]; }
    for (int n = t; n < Nc; n += TM) {
        s_S[n] = 0.f; s_bel[n] = 0.f;
        s_lm[n]  = llrs[n] * marg_llr[n];
        s_ome[n] = 1.f - errors[b * Nc + n];
    }
    __syncthreads();

    float loss = 0.f;
    float4 wd = g_cwde4[t];
    float4 bs = g_cbse4[t];

    for (int l = 0; l < Lc; l++) {
        // Phase 1: variable-node sums S[n] += msg * w_de
        atomicAdd(&s_S[c4.x], msg0 * wd.x);
        atomicAdd(&s_S[c4.y], msg1 * wd.y);
        atomicAdd(&s_S[c4.z], msg2 * wd.z);
        atomicAdd(&s_S[c4.w], msg3 * wd.w);
        __syncthreads();

        // Phase 2: d = tanh(msg_en/2) (HW tanh), local half-row product
        float me0 = bs.x + s_S[c4.x] - msg0;
        float me1 = bs.y + s_S[c4.y] - msg1;
        float me2 = bs.z + s_S[c4.z] - msg2;
        float me3 = bs.w + s_S[c4.w] - msg3;
        float d0 = tanh_fast(0.5f * me0); if (d0 == 0.f) d0 = 1.f;
        float d1 = tanh_fast(0.5f * me1); if (d1 == 0.f) d1 = 1.f;
        float d2 = tanh_fast(0.5f * me2); if (d2 == 0.f) d2 = 1.f;
        float d3 = tanh_fast(0.5f * me3); if (d3 == 0.f) d3 = 1.f;
        float lp = d0 * d1 * d2 * d3;
        float p  = lp * __shfl_xor_sync(0xffffffffu, lp, 1);  // full row product

        // Phase 3: check update 2*atanh(p/d) = ln((d+p)/(d-p)), + beliefs
        const float sgn = s_sign[r];
        const float rw  = s_rw[l];
        float nm0 = __logf(__fdividef(d0 + p, d0 - p)) * sgn + rw * msg0;
        float nm1 = __logf(__fdividef(d1 + p, d1 - p)) * sgn + rw * msg1;
        float nm2 = __logf(__fdividef(d2 + p, d2 - p)) * sgn + rw * msg2;
        float nm3 = __logf(__fdividef(d3 + p, d3 - p)) * sgn + rw * msg3;
        msg0 = nm0; msg1 = nm1; msg2 = nm2; msg3 = nm3;
        atomicAdd(&s_bel[c4.x], nm0 * mg4.x);
        atomicAdd(&s_bel[c4.y], nm1 * mg4.y);
        atomicAdd(&s_bel[c4.z], nm2 * mg4.z);
        atomicAdd(&s_bel[c4.w], nm3 * mg4.w);

        // Prefetch next layer's compact weights (overlaps barrier + loss)
        float4 nwd, nbs;
        if (l < Lc - 1) {
            nwd = g_cwde4[(l + 1) * E4 + t];
            nbs = g_cbse4[(l + 1) * E4 + t];
        }
        __syncthreads();

        // Phase 4: per-layer loss + re-zero accumulators
        const float rho = s_rho[l];
        for (int n = t; n < Nc; n += TM) {
            float bel = s_bel[n] + s_lm[n];
            float sp  = fmaxf(bel, 0.f) + __logf(1.f + __expf(-fabsf(bel)));
            loss += rho * (sp - s_ome[n] * bel);
            s_bel[n] = 0.f;
            s_S[n]   = 0.f;
        }
        __syncthreads();
        wd = nwd; bs = nbs;
    }

    // Block reduction -> atomic accumulate mean over batch
#pragma unroll
    for (int o = 16; o; o >>= 1) loss += __shfl_down_sync(0xffffffffu, loss, o);
    if ((t & 31) == 0) s_red[t >> 5] = loss;
    __syncthreads();
    if (t < 32) {
        float v = (t < TM / 32) ? s_red[t] : 0.f;
#pragma unroll
        for (int o = 16; o; o >>= 1) v += __shfl_down_sync(0xffffffffu, v, o);
        if (t == 0) atomicAdd(out, v * (1.f / (float)Bc));
    }
}

// ---------------------------------------------------------------------------
extern "C" void kernel_launch(void* const* d_in, const int* in_sizes, int n_in,
                              void* d_out, int out_size) {
    const float* synd  = (const float*)d_in[0];
    const float* errs  = (const float*)d_in[1];
    const float* H     = (const float*)d_in[2];
    const float* llrs  = (const float*)d_in[3];
    const float* wde   = (const float*)d_in[4];
    const float* wllr  = (const float*)d_in[5];
    const float* mde   = (const float*)d_in[6];
    const float* mllr  = (const float*)d_in[7];
    const float* resw  = (const float*)d_in[8];
    const float* rhos  = (const float*)d_in[9];
    float* out = (float*)d_out;

    k_prep<<<48, 256>>>(H, llrs, wde, wllr, mde, out);
    k_main<<<Bc, TM>>>(synd, errs, llrs, mllr, resw, rhos, out);
}

// round 7
// speedup vs baseline: 2.3505x; 1.2055x over previous
#include <cuda_runtime.h>
#include <math.h>

// Problem constants (fixed by the reference setup)
#define Bc 8
#define Mc 384
#define Nc 1536
#define Lc 20
#define RWc 8
#define Ec (Mc * RWc)     // 3072 edges
#define TM 768            // k_main threads: 2 per row, 4 edges per thread
#define E4 (Ec / 4)       // 768 float4 groups per layer
#define KCAP 16           // max column degree supported (P(exceed) ~ 1e-7)

// Dynamic shared layout (bytes):
//   ev0 : Ec floats  (next-layer S contributions,  nm * wde[l+1])
//   ev1 : Ec floats  (belief contributions,        nm * marg)
//   sS  : Nc floats  (per-column variable-node sums)
//   csc : KCAP*Nc uint16 (per-CTA column->edge lists)
#define SMEM_BYTES ((Ec + Ec + Nc) * 4 + KCAP * Nc * 2)

// Static device scratch (no allocation)
__device__ int4   g_ecol4[E4];            // edge -> column, 4 per thread
__device__ float4 g_cwde4[Lc * E4];       // compact per-edge wde, edge order
__device__ float4 g_cbse4[Lc * E4];       // compact llrs[c]*wllr[l][c]
__device__ float4 g_cmarg4[E4];           // compact marg_de per edge

__device__ __forceinline__ float tanh_fast(float x) {
    float y;
    asm("tanh.approx.f32 %0, %1;" : "=f"(y) : "f"(x));
    return y;
}

// ---------------------------------------------------------------------------
// k_prep: ballot-based sparsity extraction (no atomics) + weight compaction.
// 48 blocks x 256 threads: block bb owns rows [8*bb, 8*bb+8), warp w = row.
// ---------------------------------------------------------------------------
__global__ void __launch_bounds__(256) k_prep(
    const float* __restrict__ H,
    const float* __restrict__ llrs,
    const float* __restrict__ wde,
    const float* __restrict__ wllr,
    const float* __restrict__ marg_de,
    float* __restrict__ out)
{
    const int bb = blockIdx.x, t = threadIdx.x;
    const int w = t >> 5, lane = t & 31;
    const int row = bb * 8 + w;

    // --- extract: warp scans 1536 cols in 48 ballot steps, prefetched ---
    const float* Hr = H + row * Nc;
    int base = 0;
    float v = Hr[lane];
#pragma unroll 4
    for (int step = 0; step < 48; step++) {
        float cur = v;
        if (step < 47) v = Hr[(step + 1) * 32 + lane];
        unsigned mask = __ballot_sync(0xffffffffu, cur != 0.f);
        if (cur != 0.f) {
            int slot = base + __popc(mask & ((1u << lane) - 1u));
            ((int*)g_ecol4)[row * RWc + slot] = step * 32 + lane;
        }
        base += __popc(mask);
    }
    __syncthreads();

    // --- gather: this block's 64 edges x 20 layers ---
    const int ebase = bb * 64;
    for (int i = t; i < 64 * Lc; i += 256) {
        int l  = i >> 6;
        int eo = i & 63;
        int e  = ebase + eo;
        int c  = ((int*)g_ecol4)[e];
        int m  = e >> 3;
        ((float*)g_cwde4)[l * Ec + e] = wde[(l * Mc + m) * Nc + c];
        ((float*)g_cbse4)[l * Ec + e] = llrs[c] * wllr[l * Nc + c];
        if (l == 0) ((float*)g_cmarg4)[e] = marg_de[m * Nc + c];
    }
    if (bb == 0 && t == 0) out[0] = 0.f;
}

// ---------------------------------------------------------------------------
// k_main: one CTA per batch. Thread t owns edges 4t..4t+3 (half of row t>>1)
// on the row side, and columns {t, t+768} on the column side.
// Per layer: 2 barriers, 0 atomics.
//   C : read S, tanh, row product (shfl), nm; store nm*marg and nm*wde[l+1]
//   BD: per-column CSC gather -> S[c] for next layer + beliefs/loss for this
// ---------------------------------------------------------------------------
__global__ void __launch_bounds__(TM, 1) k_main(
    const float* __restrict__ synd,      // (B, M, 1)
    const float* __restrict__ errors,    // (B, N)
    const float* __restrict__ llrs,      // (N)
    const float* __restrict__ marg_llr,  // (N)
    const float* __restrict__ resw,      // (L)
    const float* __restrict__ rhos,      // (L)
    float* __restrict__ out)
{
    extern __shared__ unsigned char smem[];
    float*  ev0 = (float*)smem;                 // Ec
    float*  ev1 = ev0 + Ec;                     // Ec
    float*  sS  = ev1 + Ec;                     // Nc
    unsigned short* csc = (unsigned short*)(sS + Nc);  // KCAP*Nc
    float4* ev0f4 = (float4*)ev0;
    float4* ev1f4 = (float4*)ev1;

    __shared__ float s_rw[Lc], s_rho[Lc];
    __shared__ float s_red[TM / 32];

    const int b = blockIdx.x;
    const int t = threadIdx.x;
    const int r = t >> 1;
    const int c0 = t, c1 = t + TM;

    // ---- prologue: build per-CTA CSC (shared atomics, once) ----
    int* cnt = (int*)ev0;   // overlay (Nc ints fit in ev0's 12KB)
    for (int n = t; n < Nc; n += TM) cnt[n] = 0;
    __syncthreads();
    const int4 c4 = g_ecol4[t];
    {
        int s;
        s = atomicAdd(&cnt[c4.x], 1); csc[s * Nc + c4.x] = (unsigned short)(4 * t + 0);
        s = atomicAdd(&cnt[c4.y], 1); csc[s * Nc + c4.y] = (unsigned short)(4 * t + 1);
        s = atomicAdd(&cnt[c4.z], 1); csc[s * Nc + c4.z] = (unsigned short)(4 * t + 2);
        s = atomicAdd(&cnt[c4.w], 1); csc[s * Nc + c4.w] = (unsigned short)(4 * t + 3);
    }
    __syncthreads();
    const int deg0 = min(cnt[c0], KCAP);
    const int deg1 = min(cnt[c1], KCAP);

    // ---- per-thread constants in registers ----
    const float4 mg4  = g_cmarg4[t];
    const float  sgn  = 1.f - 2.f * synd[b * Mc + r];
    const float  lm0  = llrs[c0] * marg_llr[c0];
    const float  lm1  = llrs[c1] * marg_llr[c1];
    const float  ome0 = 1.f - errors[b * Nc + c0];
    const float  ome1 = 1.f - errors[b * Nc + c1];
    if (t < Lc) { s_rw[t] = resw[t]; s_rho[t] = rhos[t]; }

    sS[c0] = 0.f; sS[c1] = 0.f;          // layer-0 sums (msg = 0)
    float msg0 = 0.f, msg1 = 0.f, msg2 = 0.f, msg3 = 0.f;
    float4 bs  = g_cbse4[t];             // layer 0 base
    float4 nwd;                           // wde[l+1], consumed via ev0
    float  loss = 0.f;
    __syncthreads();                      // cnt overlay dead; ev0 reusable

    for (int l = 0; l < Lc; l++) {
        // ---- C: check-node update for layer l ----
        float me0 = bs.x + sS[c4.x] - msg0;
        float me1 = bs.y + sS[c4.y] - msg1;
        float me2 = bs.z + sS[c4.z] - msg2;
        float me3 = bs.w + sS[c4.w] - msg3;
        float d0 = tanh_fast(0.5f * me0); if (d0 == 0.f) d0 = 1.f;
        float d1 = tanh_fast(0.5f * me1); if (d1 == 0.f) d1 = 1.f;
        float d2 = tanh_fast(0.5f * me2); if (d2 == 0.f) d2 = 1.f;
        float d3 = tanh_fast(0.5f * me3); if (d3 == 0.f) d3 = 1.f;
        float lp = d0 * d1 * d2 * d3;
        float p  = lp * __shfl_xor_sync(0xffffffffu, lp, 1);  // full row product

        const float rw = s_rw[l];
        float nm0 = __logf(__fdividef(d0 + p, d0 - p)) * sgn + rw * msg0;
        float nm1 = __logf(__fdividef(d1 + p, d1 - p)) * sgn + rw * msg1;
        float nm2 = __logf(__fdividef(d2 + p, d2 - p)) * sgn + rw * msg2;
        float nm3 = __logf(__fdividef(d3 + p, d3 - p)) * sgn + rw * msg3;
        msg0 = nm0; msg1 = nm1; msg2 = nm2; msg3 = nm3;

        // prefetch next layer's weights (zero at last layer -> S unused)
        if (l < Lc - 1) {
            nwd = g_cwde4[(l + 1) * E4 + t];
            bs  = g_cbse4[(l + 1) * E4 + t];
        } else {
            nwd = make_float4(0.f, 0.f, 0.f, 0.f);
        }

        ev1f4[t] = make_float4(nm0 * mg4.x, nm1 * mg4.y, nm2 * mg4.z, nm3 * mg4.w);
        ev0f4[t] = make_float4(nm0 * nwd.x, nm1 * nwd.y, nm2 * nwd.z, nm3 * nwd.w);
        __syncthreads();

        // ---- BD: column gather -> S (next layer) + beliefs/loss (this layer)
        const float rho = s_rho[l];
        float S0 = 0.f, B0 = 0.f;
        for (int j = 0; j < deg0; j++) {
            int e = csc[j * Nc + c0];
            S0 += ev0[e]; B0 += ev1[e];
        }
        sS[c0] = S0;
        float bel0 = B0 + lm0;
        float sp0  = fmaxf(bel0, 0.f) + __logf(1.f + __expf(-fabsf(bel0)));
        loss += rho * (sp0 - ome0 * bel0);

        float S1 = 0.f, B1 = 0.f;
        for (int j = 0; j < deg1; j++) {
            int e = csc[j * Nc + c1];
            S1 += ev0[e]; B1 += ev1[e];
        }
        sS[c1] = S1;
        float bel1 = B1 + lm1;
        float sp1  = fmaxf(bel1, 0.f) + __logf(1.f + __expf(-fabsf(bel1)));
        loss += rho * (sp1 - ome1 * bel1);
        __syncthreads();
    }

    // ---- block reduction -> atomic accumulate mean over batch ----
#pragma unroll
    for (int o = 16; o; o >>= 1) loss += __shfl_down_sync(0xffffffffu, loss, o);
    if ((t & 31) == 0) s_red[t >> 5] = loss;
    __syncthreads();
    if (t < 32) {
        float v = (t < TM / 32) ? s_red[t] : 0.f;
#pragma unroll
        for (int o = 16; o; o >>= 1) v += __shfl_down_sync(0xffffffffu, v, o);
        if (t == 0) atomicAdd(out, v * (1.f / (float)Bc));
    }
}

// ---------------------------------------------------------------------------
extern "C" void kernel_launch(void* const* d_in, const int* in_sizes, int n_in,
                              void* d_out, int out_size) {
    const float* synd  = (const float*)d_in[0];
    const float* errs  = (const float*)d_in[1];
    const float* H     = (const float*)d_in[2];
    const float* llrs  = (const float*)d_in[3];
    const float* wde   = (const float*)d_in[4];
    const float* wllr  = (const float*)d_in[5];
    const float* mde   = (const float*)d_in[6];
    const float* mllr  = (const float*)d_in[7];
    const float* resw  = (const float*)d_in[8];
    const float* rhos  = (const float*)d_in[9];
    float* out = (float*)d_out;

    cudaFuncSetAttribute(k_main, cudaFuncAttributeMaxDynamicSharedMemorySize,
                         SMEM_BYTES);

    k_prep<<<48, 256>>>(H, llrs, wde, wllr, mde, out);
    k_main<<<Bc, TM, SMEM_BYTES>>>(synd, errs, llrs, mllr, resw, rhos, out);
}

// round 8
// speedup vs baseline: 2.7123x; 1.1539x over previous
#include <cuda_runtime.h>
#include <math.h>

// Problem constants (fixed by the reference setup)
#define Bc 8
#define Mc 384
#define Nc 1536
#define Lc 20
#define RWc 8
#define Ec (Mc * RWc)     // 3072 edges
#define TM 768            // k_main threads: 2 per row, 4 edges per thread
#define E4 (Ec / 4)       // 768 float4 groups per layer
#define EVCAP 8192        // padded slot capacity (actual ~5700)

// Dynamic shared layout (floats/ints):
//   ev0 : EVCAP floats  (next-layer S contributions, column-sorted slots)
//   ev1 : EVCAP floats  (belief contributions,       column-sorted slots)
//   sS  : Nc floats     (per-column variable-node sums)
//   col : Nc ints       (cnt during prologue -> colstart after scan)
#define SMEM_BYTES ((EVCAP + EVCAP + Nc) * 4 + Nc * 4)

// Static device scratch (no allocation)
__device__ int4   g_ecol4[E4];            // edge -> column, 4 per thread
__device__ float4 g_cwde4[Lc * E4];       // compact per-edge wde, edge order
__device__ float4 g_cbse4[Lc * E4];       // compact llrs[c]*wllr[l][c]
__device__ float4 g_cmarg4[E4];           // compact marg_de per edge

__device__ __forceinline__ float tanh_fast(float x) {
    float y;
    asm("tanh.approx.f32 %0, %1;" : "=f"(y) : "f"(x));
    return y;
}

// ---------------------------------------------------------------------------
// k_prep: ballot-based sparsity extraction (no atomics) + weight compaction.
// 48 blocks x 256 threads: block bb owns rows [8*bb, 8*bb+8), warp w = row.
// ---------------------------------------------------------------------------
__global__ void __launch_bounds__(256) k_prep(
    const float* __restrict__ H,
    const float* __restrict__ llrs,
    const float* __restrict__ wde,
    const float* __restrict__ wllr,
    const float* __restrict__ marg_de,
    float* __restrict__ out)
{
    const int bb = blockIdx.x, t = threadIdx.x;
    const int w = t >> 5, lane = t & 31;
    const int row = bb * 8 + w;

    // --- extract: warp scans 1536 cols in 48 ballot steps, prefetched ---
    const float* Hr = H + row * Nc;
    int base = 0;
    float v = Hr[lane];
#pragma unroll 4
    for (int step = 0; step < 48; step++) {
        float cur = v;
        if (step < 47) v = Hr[(step + 1) * 32 + lane];
        unsigned mask = __ballot_sync(0xffffffffu, cur != 0.f);
        if (cur != 0.f) {
            int slot = base + __popc(mask & ((1u << lane) - 1u));
            ((int*)g_ecol4)[row * RWc + slot] = step * 32 + lane;
        }
        base += __popc(mask);
    }
    __syncthreads();

    // --- gather: this block's 64 edges x 20 layers ---
    const int ebase = bb * 64;
    for (int i = t; i < 64 * Lc; i += 256) {
        int l  = i >> 6;
        int eo = i & 63;
        int e  = ebase + eo;
        int c  = ((int*)g_ecol4)[e];
        int m  = e >> 3;
        ((float*)g_cwde4)[l * Ec + e] = wde[(l * Mc + m) * Nc + c];
        ((float*)g_cbse4)[l * Ec + e] = llrs[c] * wllr[l * Nc + c];
        if (l == 0) ((float*)g_cmarg4)[e] = marg_de[m * Nc + c];
    }
    if (bb == 0 && t == 0) out[0] = 0.f;
}

// ---------------------------------------------------------------------------
// k_main: one CTA per batch. Thread t owns edges 4t..4t+3 (half of row t>>1)
// on the row side, and columns {2t, 2t+1} on the column side.
// Column data lives in 4-padded column-sorted slot arrays: row threads
// scatter-store into fixed slots, column threads read 1-2 LDS.128 per array.
// Per layer: 2 barriers, 0 atomics, no index indirection.
// ---------------------------------------------------------------------------
__global__ void __launch_bounds__(TM, 1) k_main(
    const float* __restrict__ synd,      // (B, M, 1)
    const float* __restrict__ errors,    // (B, N)
    const float* __restrict__ llrs,      // (N)
    const float* __restrict__ marg_llr,  // (N)
    const float* __restrict__ resw,      // (L)
    const float* __restrict__ rhos,      // (L)
    float* __restrict__ out)
{
    extern __shared__ unsigned char smem[];
    float* ev0 = (float*)smem;               // EVCAP
    float* ev1 = ev0 + EVCAP;                // EVCAP
    float* sS  = ev1 + EVCAP;                // Nc
    int*   col = (int*)(sS + Nc);            // Nc: cnt -> colstart

    __shared__ int   s_wsum[TM / 32], s_wscan[32];
    __shared__ float s_rw[Lc], s_rho[Lc], s_red[TM / 32];

    const int b = blockIdx.x;
    const int t = threadIdx.x;
    const int r = t >> 1;
    const int ca = 2 * t, cb = 2 * t + 1;
    const int lane = t & 31, wid = t >> 5;

    // ---- prologue: zero slot arrays, count column degrees ----
    for (int i = t; i < EVCAP; i += TM) { ev0[i] = 0.f; ev1[i] = 0.f; }
    col[ca] = 0; col[cb] = 0;
    if (t < Lc) { s_rw[t] = resw[t]; s_rho[t] = rhos[t]; }
    __syncthreads();

    const int4 c4 = g_ecol4[t];
    int rk0 = atomicAdd(&col[c4.x], 1);
    int rk1 = atomicAdd(&col[c4.y], 1);
    int rk2 = atomicAdd(&col[c4.z], 1);
    int rk3 = atomicAdd(&col[c4.w], 1);
    __syncthreads();

    // padded degrees + block exclusive scan -> column segment starts
    const int dega = col[ca], degb = col[cb];
    const int pad_a = (dega + 3) & ~3, pad_b = (degb + 3) & ~3;
    const int tsum = pad_a + pad_b;
    int x = tsum;
#pragma unroll
    for (int o = 1; o < 32; o <<= 1) {
        int y = __shfl_up_sync(0xffffffffu, x, o);
        if (lane >= o) x += y;
    }
    if (lane == 31) s_wsum[wid] = x;
    __syncthreads();
    if (t < 32) {
        int vv = (t < TM / 32) ? s_wsum[t] : 0;
#pragma unroll
        for (int o = 1; o < 32; o <<= 1) {
            int y = __shfl_up_sync(0xffffffffu, vv, o);
            if (t >= o) vv += y;
        }
        s_wscan[t] = vv;
    }
    __syncthreads();
    const int tbase  = (wid ? s_wscan[wid - 1] : 0) + (x - tsum);
    const int starta = tbase, startb = tbase + pad_a;
    col[ca] = starta; col[cb] = startb;   // overwrite cnt with colstart
    __syncthreads();

    const int sl0 = col[c4.x] + rk0;
    const int sl1 = col[c4.y] + rk1;
    const int sl2 = col[c4.z] + rk2;
    const int sl3 = col[c4.w] + rk3;
    const int pass_a = pad_a >> 2, pass_b = pad_b >> 2;
    const int s4a = starta >> 2, s4b = startb >> 2;

    // ---- per-thread constants in registers ----
    const float4 mg4 = g_cmarg4[t];
    const float  sgn = 1.f - 2.f * synd[b * Mc + r];
    const float  lma = llrs[ca] * marg_llr[ca];
    const float  lmb = llrs[cb] * marg_llr[cb];
    const float  oma = 1.f - errors[b * Nc + ca];
    const float  omb = 1.f - errors[b * Nc + cb];

    sS[ca] = 0.f; sS[cb] = 0.f;          // layer-0 sums (msg = 0)
    float msg0 = 0.f, msg1 = 0.f, msg2 = 0.f, msg3 = 0.f;
    float4 bs = g_cbse4[t];              // layer-0 base
    float loss = 0.f;
    __syncthreads();

    for (int l = 0; l < Lc; l++) {
        // Issue next-layer weight prefetch FIRST; MUFU chain below hides L2.
        float4 nwd, nbs;
        if (l < Lc - 1) {
            nwd = g_cwde4[(l + 1) * E4 + t];
            nbs = g_cbse4[(l + 1) * E4 + t];
        } else {
            nwd = make_float4(0.f, 0.f, 0.f, 0.f);
            nbs = bs;
        }

        // ---- C: check-node update for layer l ----
        float me0 = bs.x + sS[c4.x] - msg0;
        float me1 = bs.y + sS[c4.y] - msg1;
        float me2 = bs.z + sS[c4.z] - msg2;
        float me3 = bs.w + sS[c4.w] - msg3;
        float d0 = tanh_fast(0.5f * me0); if (d0 == 0.f) d0 = 1.f;
        float d1 = tanh_fast(0.5f * me1); if (d1 == 0.f) d1 = 1.f;
        float d2 = tanh_fast(0.5f * me2); if (d2 == 0.f) d2 = 1.f;
        float d3 = tanh_fast(0.5f * me3); if (d3 == 0.f) d3 = 1.f;
        float lp = d0 * d1 * d2 * d3;
        float p  = lp * __shfl_xor_sync(0xffffffffu, lp, 1);  // full row product

        const float rw = s_rw[l];
        float nm0 = __logf(__fdividef(d0 + p, d0 - p)) * sgn + rw * msg0;
        float nm1 = __logf(__fdividef(d1 + p, d1 - p)) * sgn + rw * msg1;
        float nm2 = __logf(__fdividef(d2 + p, d2 - p)) * sgn + rw * msg2;
        float nm3 = __logf(__fdividef(d3 + p, d3 - p)) * sgn + rw * msg3;
        msg0 = nm0; msg1 = nm1; msg2 = nm2; msg3 = nm3;

        // Scatter into column-sorted slots (no indirection on the read side)
        ev0[sl0] = nm0 * nwd.x;  ev1[sl0] = nm0 * mg4.x;
        ev0[sl1] = nm1 * nwd.y;  ev1[sl1] = nm1 * mg4.y;
        ev0[sl2] = nm2 * nwd.z;  ev1[sl2] = nm2 * mg4.z;
        ev0[sl3] = nm3 * nwd.w;  ev1[sl3] = nm3 * mg4.w;
        bs = nbs;
        __syncthreads();

        // ---- BD: contiguous vector gather -> S (next layer) + loss (this)
        const float rho = s_rho[l];
        float Sa = 0.f, Ba = 0.f;
        for (int j = 0; j < pass_a; j++) {
            float4 v = ((const float4*)ev0)[s4a + j];
            float4 u = ((const float4*)ev1)[s4a + j];
            Sa += (v.x + v.y) + (v.z + v.w);
            Ba += (u.x + u.y) + (u.z + u.w);
        }
        sS[ca] = Sa;
        float bela = Ba + lma;
        float spa  = fmaxf(bela, 0.f) + __logf(1.f + __expf(-fabsf(bela)));
        loss += rho * (spa - oma * bela);

        float Sb = 0.f, Bb = 0.f;
        for (int j = 0; j < pass_b; j++) {
            float4 v = ((const float4*)ev0)[s4b + j];
            float4 u = ((const float4*)ev1)[s4b + j];
            Sb += (v.x + v.y) + (v.z + v.w);
            Bb += (u.x + u.y) + (u.z + u.w);
        }
        sS[cb] = Sb;
        float belb = Bb + lmb;
        float spb  = fmaxf(belb, 0.f) + __logf(1.f + __expf(-fabsf(belb)));
        loss += rho * (spb - omb * belb);
        __syncthreads();
    }

    // ---- block reduction -> atomic accumulate mean over batch ----
#pragma unroll
    for (int o = 16; o; o >>= 1) loss += __shfl_down_sync(0xffffffffu, loss, o);
    if (lane == 0) s_red[wid] = loss;
    __syncthreads();
    if (t < 32) {
        float v = (t < TM / 32) ? s_red[t] : 0.f;
#pragma unroll
        for (int o = 16; o; o >>= 1) v += __shfl_down_sync(0xffffffffu, v, o);
        if (t == 0) atomicAdd(out, v * (1.f / (float)Bc));
    }
}

// ---------------------------------------------------------------------------
extern "C" void kernel_launch(void* const* d_in, const int* in_sizes, int n_in,
                              void* d_out, int out_size) {
    const float* synd  = (const float*)d_in[0];
    const float* errs  = (const float*)d_in[1];
    const float* H     = (const float*)d_in[2];
    const float* llrs  = (const float*)d_in[3];
    const float* wde   = (const float*)d_in[4];
    const float* wllr  = (const float*)d_in[5];
    const float* mde   = (const float*)d_in[6];
    const float* mllr  = (const float*)d_in[7];
    const float* resw  = (const float*)d_in[8];
    const float* rhos  = (const float*)d_in[9];
    float* out = (float*)d_out;

    cudaFuncSetAttribute(k_main, cudaFuncAttributeMaxDynamicSharedMemorySize,
                         SMEM_BYTES);

    k_prep<<<48, 256>>>(H, llrs, wde, wllr, mde, out);
    k_main<<<Bc, TM, SMEM_BYTES>>>(synd, errs, llrs, mllr, resw, rhos, out);
}

// round 10
// speedup vs baseline: 2.9610x; 1.0917x over previous
#include <cuda_runtime.h>
#include <math.h>

// Problem constants (fixed by the reference setup)
#define Bc 8
#define Mc 384
#define Nc 1536
#define Lc 20
#define RWc 8
#define Ec (Mc * RWc)     // 3072 edges
#define TM 768            // k_main threads: 2 per row, 4 edges per thread
#define E4 (Ec / 4)       // 768 float4 groups per layer
#define EV2CAP 6144       // float2 slot capacity (worst case 4608)

// Dynamic shared layout:
//   ev  : EV2CAP float2 (interleaved {S-contrib, belief-contrib} slots,
//                        column-sorted, 2-slot padded)
//   sS  : Nc floats     (per-column variable-node sums)
//   col : Nc ints       (cnt during prologue -> colstart after scan)
#define SMEM_BYTES (EV2CAP * 8 + Nc * 4 + Nc * 4)

// Static device scratch (no allocation)
__device__ int4   g_ecol4[E4];            // edge -> column, 4 per thread
__device__ float4 g_cwde4[Lc * E4];       // compact per-edge wde, edge order
__device__ float4 g_cbse4[Lc * E4];       // compact llrs[c]*wllr[l][c]
__device__ float4 g_cmarg4[E4];           // compact marg_de per edge
__device__ float  g_bel[Bc * Lc * Nc];    // per-layer beliefs (for k_loss)

__device__ __forceinline__ float tanh_fast(float x) {
    float y;
    asm("tanh.approx.f32 %0, %1;" : "=f"(y) : "f"(x));
    return y;
}

// ---------------------------------------------------------------------------
// k_prep: ballot-based sparsity extraction (no atomics) + weight compaction.
// 96 blocks x 128 threads: block bb owns rows [4*bb, 4*bb+4), warp w = row.
// ---------------------------------------------------------------------------
__global__ void __launch_bounds__(128) k_prep(
    const float* __restrict__ H,
    const float* __restrict__ llrs,
    const float* __restrict__ wde,
    const float* __restrict__ wllr,
    const float* __restrict__ marg_de,
    float* __restrict__ out)
{
    const int bb = blockIdx.x, t = threadIdx.x;
    const int w = t >> 5, lane = t & 31;
    const int row = bb * 4 + w;

    // --- extract: warp scans 1536 cols in 48 ballot steps, prefetched ---
    const float* Hr = H + row * Nc;
    int base = 0;
    float v = Hr[lane];
#pragma unroll 4
    for (int step = 0; step < 48; step++) {
        float cur = v;
        if (step < 47) v = Hr[(step + 1) * 32 + lane];
        unsigned mask = __ballot_sync(0xffffffffu, cur != 0.f);
        if (cur != 0.f) {
            int slot = base + __popc(mask & ((1u << lane) - 1u));
            ((int*)g_ecol4)[row * RWc + slot] = step * 32 + lane;
        }
        base += __popc(mask);
    }
    __syncthreads();

    // --- gather: this block's 32 edges x 20 layers ---
    const int ebase = bb * 32;
    for (int i = t; i < 32 * Lc; i += 128) {
        int l  = i >> 5;
        int eo = i & 31;
        int e  = ebase + eo;
        int c  = ((int*)g_ecol4)[e];
        int m  = e >> 3;
        ((float*)g_cwde4)[l * Ec + e] = wde[(l * Mc + m) * Nc + c];
        ((float*)g_cbse4)[l * Ec + e] = llrs[c] * wllr[l * Nc + c];
        if (l == 0) ((float*)g_cmarg4)[e] = marg_de[m * Nc + c];
    }
    if (bb == 0 && t == 0) out[0] = 0.f;
}

// ---------------------------------------------------------------------------
// k_main: one CTA per batch. Thread t owns edges 4t..4t+3 (half of row t>>1)
// on the row side, columns {2t, 2t+1} on the column side. Column data lives
// in interleaved float2 slots {S-contrib, belief-contrib}, column-sorted and
// 2-padded so BD reads float4s (mostly one per column). Beliefs stream to
// gmem; loss is computed by k_loss on the full chip afterward.
// Per layer: 2 barriers, 0 atomics, 4 STS.64 scatters, ~2 LDS.128 gathers.
// ---------------------------------------------------------------------------
__global__ void __launch_bounds__(TM, 1) k_main(
    const float* __restrict__ synd,      // (B, M, 1)
    const float* __restrict__ llrs,      // (N)
    const float* __restrict__ marg_llr,  // (N)
    const float* __restrict__ resw)      // (L)
{
    extern __shared__ unsigned char smem[];
    float2* ev  = (float2*)smem;             // EV2CAP
    float*  sS  = (float*)(ev + EV2CAP);     // Nc
    int*    col = (int*)(sS + Nc);           // Nc: cnt -> colstart

    __shared__ int   s_wsum[TM / 32], s_wscan[32];
    __shared__ float s_rw[Lc];

    const int b = blockIdx.x;
    const int t = threadIdx.x;
    const int r = t >> 1;
    const int ca = 2 * t, cb = 2 * t + 1;
    const int lane = t & 31, wid = t >> 5;

    // ---- prologue: zero slots, count column degrees ----
    for (int i = t; i < EV2CAP; i += TM) ev[i] = make_float2(0.f, 0.f);
    col[ca] = 0; col[cb] = 0;
    if (t < Lc) s_rw[t] = resw[t];
    __syncthreads();

    const int4 c4 = g_ecol4[t];
    int rk0 = atomicAdd(&col[c4.x], 1);
    int rk1 = atomicAdd(&col[c4.y], 1);
    int rk2 = atomicAdd(&col[c4.z], 1);
    int rk3 = atomicAdd(&col[c4.w], 1);
    __syncthreads();

    // 2-padded degrees + block exclusive scan -> even column segment starts
    const int dega = col[ca], degb = col[cb];
    const int pad_a = (dega + 1) & ~1, pad_b = (degb + 1) & ~1;
    const int tsum = pad_a + pad_b;
    int x = tsum;
#pragma unroll
    for (int o = 1; o < 32; o <<= 1) {
        int y = __shfl_up_sync(0xffffffffu, x, o);
        if (lane >= o) x += y;
    }
    if (lane == 31) s_wsum[wid] = x;
    __syncthreads();
    if (t < 32) {
        int vv = (t < TM / 32) ? s_wsum[t] : 0;
#pragma unroll
        for (int o = 1; o < 32; o <<= 1) {
            int y = __shfl_up_sync(0xffffffffu, vv, o);
            if (t >= o) vv += y;
        }
        s_wscan[t] = vv;
    }
    __syncthreads();
    const int tbase  = (wid ? s_wscan[wid - 1] : 0) + (x - tsum);
    const int starta = tbase, startb = tbase + pad_a;
    col[ca] = starta; col[cb] = startb;   // overwrite cnt with colstart
    __syncthreads();

    const int sl0 = col[c4.x] + rk0;
    const int sl1 = col[c4.y] + rk1;
    const int sl2 = col[c4.z] + rk2;
    const int sl3 = col[c4.w] + rk3;
    const int pass_a = pad_a >> 1, pass_b = pad_b >> 1;  // float4 reads
    const int s4a = starta >> 1, s4b = startb >> 1;

    // ---- per-thread constants in registers ----
    const float4 mg4 = g_cmarg4[t];
    const float  sgn = 1.f - 2.f * synd[b * Mc + r];
    const float  lma = llrs[ca] * marg_llr[ca];
    const float  lmb = llrs[cb] * marg_llr[cb];
    float* belrow = g_bel + (b * Lc) * Nc;   // + l*Nc per layer

    ((float2*)sS)[t] = make_float2(0.f, 0.f);  // layer-0 sums (msg = 0)
    float msg0 = 0.f, msg1 = 0.f, msg2 = 0.f, msg3 = 0.f;
    float4 bs = g_cbse4[t];              // layer-0 base
    __syncthreads();

    for (int l = 0; l < Lc; l++) {
        // Issue next-layer weight prefetch FIRST; MUFU chain below hides L2.
        float4 nwd, nbs;
        if (l < Lc - 1) {
            nwd = g_cwde4[(l + 1) * E4 + t];
            nbs = g_cbse4[(l + 1) * E4 + t];
        } else {
            nwd = make_float4(0.f, 0.f, 0.f, 0.f);
            nbs = bs;
        }

        // ---- C: check-node update for layer l ----
        float me0 = bs.x + sS[c4.x] - msg0;
        float me1 = bs.y + sS[c4.y] - msg1;
        float me2 = bs.z + sS[c4.z] - msg2;
        float me3 = bs.w + sS[c4.w] - msg3;
        float d0 = tanh_fast(0.5f * me0); if (d0 == 0.f) d0 = 1.f;
        float d1 = tanh_fast(0.5f * me1); if (d1 == 0.f) d1 = 1.f;
        float d2 = tanh_fast(0.5f * me2); if (d2 == 0.f) d2 = 1.f;
        float d3 = tanh_fast(0.5f * me3); if (d3 == 0.f) d3 = 1.f;
        float lp = d0 * d1 * d2 * d3;
        float p  = lp * __shfl_xor_sync(0xffffffffu, lp, 1);  // full row product

        const float rw = s_rw[l];
        float nm0 = __logf(__fdividef(d0 + p, d0 - p)) * sgn + rw * msg0;
        float nm1 = __logf(__fdividef(d1 + p, d1 - p)) * sgn + rw * msg1;
        float nm2 = __logf(__fdividef(d2 + p, d2 - p)) * sgn + rw * msg2;
        float nm3 = __logf(__fdividef(d3 + p, d3 - p)) * sgn + rw * msg3;
        msg0 = nm0; msg1 = nm1; msg2 = nm2; msg3 = nm3;

        // Scatter interleaved {S-contrib, belief-contrib} slots (STS.64 x4)
        ev[sl0] = make_float2(nm0 * nwd.x, nm0 * mg4.x);
        ev[sl1] = make_float2(nm1 * nwd.y, nm1 * mg4.y);
        ev[sl2] = make_float2(nm2 * nwd.z, nm2 * mg4.z);
        ev[sl3] = make_float2(nm3 * nwd.w, nm3 * mg4.w);
        bs = nbs;
        __syncthreads();

        // ---- BD: contiguous float4 gather -> S (next layer) + beliefs ----
        float Sa = 0.f, Ba = 0.f;
        for (int j = 0; j < pass_a; j++) {
            float4 v = ((const float4*)ev)[s4a + j];
            Sa += v.x + v.z;  Ba += v.y + v.w;
        }
        float Sb = 0.f, Bb = 0.f;
        for (int j = 0; j < pass_b; j++) {
            float4 v = ((const float4*)ev)[s4b + j];
            Sb += v.x + v.z;  Bb += v.y + v.w;
        }
        ((float2*)sS)[t] = make_float2(Sa, Sb);
        ((float2*)(belrow + l * Nc))[t] = make_float2(Ba + lma, Bb + lmb);
        __syncthreads();
    }
}

// ---------------------------------------------------------------------------
// k_loss: full-chip softplus + weighted reduction over all (b, l, c).
// ---------------------------------------------------------------------------
__global__ void __launch_bounds__(1024) k_loss(
    const float* __restrict__ errors,    // (B, N)
    const float* __restrict__ rhos,      // (L)
    float* __restrict__ out)
{
    __shared__ float s_red[32];
    const int i = blockIdx.x * 1024 + threadIdx.x;   // grid covers Bc*Lc*Nc
    const int c = i % Nc;
    const int l = (i / Nc) % Lc;
    const int b = i / (Lc * Nc);

    float bel = g_bel[i];
    float sp  = fmaxf(bel, 0.f) + __logf(1.f + __expf(-fabsf(bel)));
    float v   = rhos[l] * (sp - (1.f - errors[b * Nc + c]) * bel);

#pragma unroll
    for (int o = 16; o; o >>= 1) v += __shfl_down_sync(0xffffffffu, v, o);
    const int lane = threadIdx.x & 31, wid = threadIdx.x >> 5;
    if (lane == 0) s_red[wid] = v;
    __syncthreads();
    if (threadIdx.x < 32) {
        float s = s_red[threadIdx.x];
#pragma unroll
        for (int o = 16; o; o >>= 1) s += __shfl_down_sync(0xffffffffu, s, o);
        if (threadIdx.x == 0) atomicAdd(out, s * (1.f / (float)Bc));
    }
}

// ---------------------------------------------------------------------------
extern "C" void kernel_launch(void* const* d_in, const int* in_sizes, int n_in,
                              void* d_out, int out_size) {
    const float* synd  = (const float*)d_in[0];
    const float* errs  = (const float*)d_in[1];
    const float* H     = (const float*)d_in[2];
    const float* llrs  = (const float*)d_in[3];
    const float* wde   = (const float*)d_in[4];
    const float* wllr  = (const float*)d_in[5];
    const float* mde   = (const float*)d_in[6];
    const float* mllr  = (const float*)d_in[7];
    const float* resw  = (const float*)d_in[8];
    const float* rhos  = (const float*)d_in[9];
    float* out = (float*)d_out;

    cudaFuncSetAttribute(k_main, cudaFuncAttributeMaxDynamicSharedMemorySize,
                         SMEM_BYTES);

    k_prep<<<96, 128>>>(H, llrs, wde, wllr, mde, out);
    k_main<<<Bc, TM, SMEM_BYTES>>>(synd, llrs, mllr, resw);
    k_loss<<<(Bc * Lc * Nc) / 1024, 1024>>>(errs, rhos, out);
}

// round 12
// speedup vs baseline: 2.9634x; 1.0008x over previous
#include <cuda_runtime.h>
#include <math.h>

// Problem constants (fixed by the reference setup)
#define Bc 8
#define Mc 384
#define Nc 1536
#define Lc 20
#define RWc 8
#define Ec (Mc * RWc)     // 3072 edges
#define TM 768            // k_main threads: 2 per row, 4 edges per thread
#define E4 (Ec / 4)       // 768 float4 groups per layer
#define EV2CAP 6144       // float2 slot capacity (worst case 4608)

// Dynamic shared layout:
//   ev  : EV2CAP float2 (interleaved {S-contrib, belief-contrib} slots,
//                        column-sorted, 2-slot padded)
//   sS  : Nc floats     (per-column variable-node sums)
//   col : Nc ints       (cnt during prologue -> colstart after scan)
#define SMEM_BYTES (EV2CAP * 8 + Nc * 4 + Nc * 4)

// Static device scratch (no allocation)
__device__ int    g_row_cnt[Mc];          // zero-init at load; re-zeroed by k_gather
__device__ int4   g_ecol4[E4];            // edge -> column, 4 per thread
__device__ float4 g_cwde4[Lc * E4];       // compact per-edge wde, edge order
__device__ float4 g_cbse4[Lc * E4];       // compact llrs[c]*wllr[l][c]
__device__ float4 g_cmarg4[E4];           // compact marg_de per edge
__device__ float  g_bel[Bc * Lc * Nc];    // per-layer beliefs (for k_loss)

__device__ __forceinline__ float tanh_fast(float x) {
    float y;
    asm("tanh.approx.f32 %0, %1;" : "=f"(y) : "f"(x));
    return y;
}

// ---------------------------------------------------------------------------
// k_extract: full-chip H scan, one float4 per thread (each row = 384 float4s,
// so a float4 never crosses rows). Nonzeros claim slots via per-row atomics;
// slot order within a row is irrelevant (products/scatters commute).
// Counters are zero on entry (static init on first call, k_gather re-zeroes
// them for every subsequent replay).
// ---------------------------------------------------------------------------
__global__ void __launch_bounds__(1024) k_extract(
    const float* __restrict__ H, float* __restrict__ out)
{
    const int idx = blockIdx.x * 1024 + threadIdx.x;  // Mc*Nc/4 = 147456
    const float4 h = ((const float4*)H)[idx];
    if (h.x != 0.f || h.y != 0.f || h.z != 0.f || h.w != 0.f) {
        const int m  = idx / (Nc / 4);
        const int c0 = (idx - m * (Nc / 4)) * 4;
        int* ecol = (int*)g_ecol4;
        if (h.x != 0.f) ecol[m * RWc + atomicAdd(&g_row_cnt[m], 1)] = c0 + 0;
        if (h.y != 0.f) ecol[m * RWc + atomicAdd(&g_row_cnt[m], 1)] = c0 + 1;
        if (h.z != 0.f) ecol[m * RWc + atomicAdd(&g_row_cnt[m], 1)] = c0 + 2;
        if (h.w != 0.f) ecol[m * RWc + atomicAdd(&g_row_cnt[m], 1)] = c0 + 3;
    }
    if (idx == 0) out[0] = 0.f;
}

// ---------------------------------------------------------------------------
// k_gather: one thread per (layer, edge) — 61440 threads, full-chip MLP.
// Compacts wde / llrs*wllr / marg_de into edge order; resets row counters
// for the next graph replay.
// ---------------------------------------------------------------------------
__global__ void __launch_bounds__(1024) k_gather(
    const float* __restrict__ llrs,
    const float* __restrict__ wde,
    const float* __restrict__ wllr,
    const float* __restrict__ marg_de)
{
    const int i = blockIdx.x * 1024 + threadIdx.x;  // Lc*Ec = 61440
    const int l = i / Ec;
    const int e = i - l * Ec;
    const int c = ((const int*)g_ecol4)[e];
    const int m = e >> 3;
    ((float*)g_cwde4)[i] = wde[(l * Mc + m) * Nc + c];
    ((float*)g_cbse4)[i] = llrs[c] * wllr[l * Nc + c];
    if (l == 0) {
        ((float*)g_cmarg4)[e] = marg_de[m * Nc + c];
        if (e < Mc) g_row_cnt[e] = 0;   // reset for next replay
    }
}

// ---------------------------------------------------------------------------
// k_main: one CTA per batch. Thread t owns edges 4t..4t+3 (half of row t>>1)
// on the row side, columns {2t, 2t+1} on the column side. Column data lives
// in interleaved float2 slots {S-contrib, belief-contrib}, column-sorted and
// 2-padded so BD reads float4s (mostly one per column). Beliefs stream to
// gmem; loss is computed by k_loss on the full chip afterward.
// Per layer: 2 barriers, 0 atomics, 4 STS.64 scatters, ~2 LDS.128 gathers.
// ---------------------------------------------------------------------------
__global__ void __launch_bounds__(TM, 1) k_main(
    const float* __restrict__ synd,      // (B, M, 1)
    const float* __restrict__ llrs,      // (N)
    const float* __restrict__ marg_llr,  // (N)
    const float* __restrict__ resw)      // (L)
{
    extern __shared__ unsigned char smem[];
    float2* ev  = (float2*)smem;             // EV2CAP
    float*  sS  = (float*)(ev + EV2CAP);     // Nc
    int*    col = (int*)(sS + Nc);           // Nc: cnt -> colstart

    __shared__ int   s_wsum[TM / 32], s_wscan[32];
    __shared__ float s_rw[Lc];

    const int b = blockIdx.x;
    const int t = threadIdx.x;
    const int r = t >> 1;
    const int ca = 2 * t, cb = 2 * t + 1;
    const int lane = t & 31, wid = t >> 5;

    // ---- prologue: zero slots, count column degrees ----
    for (int i = t; i < EV2CAP; i += TM) ev[i] = make_float2(0.f, 0.f);
    col[ca] = 0; col[cb] = 0;
    if (t < Lc) s_rw[t] = resw[t];
    __syncthreads();

    const int4 c4 = g_ecol4[t];
    int rk0 = atomicAdd(&col[c4.x], 1);
    int rk1 = atomicAdd(&col[c4.y], 1);
    int rk2 = atomicAdd(&col[c4.z], 1);
    int rk3 = atomicAdd(&col[c4.w], 1);
    __syncthreads();

    // 2-padded degrees + block exclusive scan -> even column segment starts
    const int dega = col[ca], degb = col[cb];
    const int pad_a = (dega + 1) & ~1, pad_b = (degb + 1) & ~1;
    const int tsum = pad_a + pad_b;
    int x = tsum;
#pragma unroll
    for (int o = 1; o < 32; o <<= 1) {
        int y = __shfl_up_sync(0xffffffffu, x, o);
        if (lane >= o) x += y;
    }
    if (lane == 31) s_wsum[wid] = x;
    __syncthreads();
    if (t < 32) {
        int vv = (t < TM / 32) ? s_wsum[t] : 0;
#pragma unroll
        for (int o = 1; o < 32; o <<= 1) {
            int y = __shfl_up_sync(0xffffffffu, vv, o);
            if (t >= o) vv += y;
        }
        s_wscan[t] = vv;
    }
    __syncthreads();
    const int tbase  = (wid ? s_wscan[wid - 1] : 0) + (x - tsum);
    const int starta = tbase, startb = tbase + pad_a;
    col[ca] = starta; col[cb] = startb;   // overwrite cnt with colstart
    __syncthreads();

    const int sl0 = col[c4.x] + rk0;
    const int sl1 = col[c4.y] + rk1;
    const int sl2 = col[c4.z] + rk2;
    const int sl3 = col[c4.w] + rk3;
    const int pass_a = pad_a >> 1, pass_b = pad_b >> 1;  // float4 reads
    const int s4a = starta >> 1, s4b = startb >> 1;

    // ---- per-thread constants in registers ----
    const float4 mg4 = g_cmarg4[t];
    const float  sgn = 1.f - 2.f * synd[b * Mc + r];
    const float  lma = llrs[ca] * marg_llr[ca];
    const float  lmb = llrs[cb] * marg_llr[cb];
    float* belrow = g_bel + (b * Lc) * Nc;   // + l*Nc per layer

    ((float2*)sS)[t] = make_float2(0.f, 0.f);  // layer-0 sums (msg = 0)
    float msg0 = 0.f, msg1 = 0.f, msg2 = 0.f, msg3 = 0.f;
    float4 bs = g_cbse4[t];              // layer-0 base
    __syncthreads();

    for (int l = 0; l < Lc; l++) {
        // Issue next-layer weight prefetch FIRST; MUFU chain below hides L2.
        float4 nwd, nbs;
        if (l < Lc - 1) {
            nwd = g_cwde4[(l + 1) * E4 + t];
            nbs = g_cbse4[(l + 1) * E4 + t];
        } else {
            nwd = make_float4(0.f, 0.f, 0.f, 0.f);
            nbs = bs;
        }

        // ---- C: check-node update for layer l ----
        float me0 = bs.x + sS[c4.x] - msg0;
        float me1 = bs.y + sS[c4.y] - msg1;
        float me2 = bs.z + sS[c4.z] - msg2;
        float me3 = bs.w + sS[c4.w] - msg3;
        float d0 = tanh_fast(0.5f * me0); if (d0 == 0.f) d0 = 1.f;
        float d1 = tanh_fast(0.5f * me1); if (d1 == 0.f) d1 = 1.f;
        float d2 = tanh_fast(0.5f * me2); if (d2 == 0.f) d2 = 1.f;
        float d3 = tanh_fast(0.5f * me3); if (d3 == 0.f) d3 = 1.f;
        float lp = d0 * d1 * d2 * d3;
        float p  = lp * __shfl_xor_sync(0xffffffffu, lp, 1);  // full row product

        const float rw = s_rw[l];
        float nm0 = __logf(__fdividef(d0 + p, d0 - p)) * sgn + rw * msg0;
        float nm1 = __logf(__fdividef(d1 + p, d1 - p)) * sgn + rw * msg1;
        float nm2 = __logf(__fdividef(d2 + p, d2 - p)) * sgn + rw * msg2;
        float nm3 = __logf(__fdividef(d3 + p, d3 - p)) * sgn + rw * msg3;
        msg0 = nm0; msg1 = nm1; msg2 = nm2; msg3 = nm3;

        // Scatter interleaved {S-contrib, belief-contrib} slots (STS.64 x4)
        ev[sl0] = make_float2(nm0 * nwd.x, nm0 * mg4.x);
        ev[sl1] = make_float2(nm1 * nwd.y, nm1 * mg4.y);
        ev[sl2] = make_float2(nm2 * nwd.z, nm2 * mg4.z);
        ev[sl3] = make_float2(nm3 * nwd.w, nm3 * mg4.w);
        bs = nbs;
        __syncthreads();

        // ---- BD: contiguous float4 gather -> S (next layer) + beliefs ----
        float Sa = 0.f, Ba = 0.f;
        for (int j = 0; j < pass_a; j++) {
            float4 v = ((const float4*)ev)[s4a + j];
            Sa += v.x + v.z;  Ba += v.y + v.w;
        }
        float Sb = 0.f, Bb = 0.f;
        for (int j = 0; j < pass_b; j++) {
            float4 v = ((const float4*)ev)[s4b + j];
            Sb += v.x + v.z;  Bb += v.y + v.w;
        }
        ((float2*)sS)[t] = make_float2(Sa, Sb);
        ((float2*)(belrow + l * Nc))[t] = make_float2(Ba + lma, Bb + lmb);
        __syncthreads();
    }
}

// ---------------------------------------------------------------------------
// k_loss: full-chip softplus + weighted reduction over all (b, l, c).
// ---------------------------------------------------------------------------
__global__ void __launch_bounds__(1024) k_loss(
    const float* __restrict__ errors,    // (B, N)
    const float* __restrict__ rhos,      // (L)
    float* __restrict__ out)
{
    __shared__ float s_red[32];
    const int i = blockIdx.x * 1024 + threadIdx.x;   // grid covers Bc*Lc*Nc
    const int c = i % Nc;
    const int l = (i / Nc) % Lc;
    const int b = i / (Lc * Nc);

    float bel = g_bel[i];
    float sp  = fmaxf(bel, 0.f) + __logf(1.f + __expf(-fabsf(bel)));
    float v   = rhos[l] * (sp - (1.f - errors[b * Nc + c]) * bel);

#pragma unroll
    for (int o = 16; o; o >>= 1) v += __shfl_down_sync(0xffffffffu, v, o);
    const int lane = threadIdx.x & 31, wid = threadIdx.x >> 5;
    if (lane == 0) s_red[wid] = v;
    __syncthreads();
    if (threadIdx.x < 32) {
        float s = s_red[threadIdx.x];
#pragma unroll
        for (int o = 16; o; o >>= 1) s += __shfl_down_sync(0xffffffffu, s, o);
        if (threadIdx.x == 0) atomicAdd(out, s * (1.f / (float)Bc));
    }
}

// ---------------------------------------------------------------------------
extern "C" void kernel_launch(void* const* d_in, const int* in_sizes, int n_in,
                              void* d_out, int out_size) {
    const float* synd  = (const float*)d_in[0];
    const float* errs  = (const float*)d_in[1];
    const float* H     = (const float*)d_in[2];
    const float* llrs  = (const float*)d_in[3];
    const float* wde   = (const float*)d_in[4];
    const float* wllr  = (const float*)d_in[5];
    const float* mde   = (const float*)d_in[6];
    const float* mllr  = (const float*)d_in[7];
    const float* resw  = (const float*)d_in[8];
    const float* rhos  = (const float*)d_in[9];
    float* out = (float*)d_out;

    cudaFuncSetAttribute(k_main, cudaFuncAttributeMaxDynamicSharedMemorySize,
                         SMEM_BYTES);

    k_extract<<<(Mc * Nc / 4) / 1024, 1024>>>(H, out);
    k_gather<<<(Lc * Ec) / 1024, 1024>>>(llrs, wde, wllr, mde);
    k_main<<<Bc, TM, SMEM_BYTES>>>(synd, llrs, mllr, resw);
    k_loss<<<(Bc * Lc * Nc) / 1024, 1024>>>(errs, rhos, out);
}